// round 1
// baseline (speedup 1.0000x reference)
#include <cuda_runtime.h>
#include <math.h>

// ---------------------------------------------------------------------------
// Problem constants
// ---------------------------------------------------------------------------
#define D_MODEL 1024
#define T_LEN   2048
#define BATCH   2
#define N_HEADS 16
#define D_HEAD  64
#define BT      (BATCH * T_LEN)          // 4096 rows
#define W_ELEMS (D_MODEL * D_MODEL)      // 1048576

// ---------------------------------------------------------------------------
// Scratch (static device memory; no runtime allocation allowed)
// ---------------------------------------------------------------------------
__device__ float  g_Wt[4][W_ELEMS];                  // ternarized weights (alpha folded in)
__device__ float  g_Q[BT * D_MODEL];
__device__ float  g_K[BT * D_MODEL];
__device__ float  g_V[BT * D_MODEL];
__device__ float  g_O[BT * D_MODEL];                 // attention output
__device__ float  g_Y[BT * D_MODEL];                 // pre-quant final
__device__ float  g_S[(size_t)BATCH * N_HEADS * T_LEN * T_LEN]; // 512 MB scores
__device__ double g_red[4][1024];
__device__ double g_red2a[4][1024];
__device__ double g_red2b[4][1024];
__device__ float  g_delta[4];
__device__ float  g_alpha[4];
__device__ float  g_maxp[4096];
__device__ float  g_scale;

// ---------------------------------------------------------------------------
// Weight ternarization statistics
// ---------------------------------------------------------------------------
__device__ __forceinline__ const float* pick_w(const float* W0, const float* W1,
                                               const float* W2, const float* W3, int y) {
    return y == 0 ? W0 : (y == 1 ? W1 : (y == 2 ? W2 : W3));
}

__global__ void k_wabs(const float* __restrict__ W0, const float* __restrict__ W1,
                       const float* __restrict__ W2, const float* __restrict__ W3) {
    const float* W = pick_w(W0, W1, W2, W3, blockIdx.y);
    __shared__ double sm[256];
    int base = blockIdx.x * 1024;
    double s = 0.0;
    for (int i = threadIdx.x; i < 1024; i += 256)
        s += (double)fabsf(W[base + i]);
    sm[threadIdx.x] = s;
    __syncthreads();
    for (int st = 128; st > 0; st >>= 1) {
        if (threadIdx.x < st) sm[threadIdx.x] += sm[threadIdx.x + st];
        __syncthreads();
    }
    if (threadIdx.x == 0) g_red[blockIdx.y][blockIdx.x] = sm[0];
}

__global__ void k_wstat1() {
    __shared__ double sm[256];
    double s = 0.0;
    for (int i = threadIdx.x; i < 1024; i += 256) s += g_red[blockIdx.x][i];
    sm[threadIdx.x] = s;
    __syncthreads();
    for (int st = 128; st > 0; st >>= 1) {
        if (threadIdx.x < st) sm[threadIdx.x] += sm[threadIdx.x + st];
        __syncthreads();
    }
    if (threadIdx.x == 0)
        g_delta[blockIdx.x] = (float)(0.05 * (sm[0] / (double)W_ELEMS));
}

__global__ void k_wmask(const float* __restrict__ W0, const float* __restrict__ W1,
                        const float* __restrict__ W2, const float* __restrict__ W3) {
    const float* W = pick_w(W0, W1, W2, W3, blockIdx.y);
    float delta = g_delta[blockIdx.y];
    __shared__ double sa[256];
    __shared__ double sb[256];
    int base = blockIdx.x * 1024;
    double s1 = 0.0, s2 = 0.0;
    for (int i = threadIdx.x; i < 1024; i += 256) {
        float a = fabsf(W[base + i]);
        if (a > delta) { s1 += (double)a; s2 += 1.0; }
    }
    sa[threadIdx.x] = s1; sb[threadIdx.x] = s2;
    __syncthreads();
    for (int st = 128; st > 0; st >>= 1) {
        if (threadIdx.x < st) {
            sa[threadIdx.x] += sa[threadIdx.x + st];
            sb[threadIdx.x] += sb[threadIdx.x + st];
        }
        __syncthreads();
    }
    if (threadIdx.x == 0) {
        g_red2a[blockIdx.y][blockIdx.x] = sa[0];
        g_red2b[blockIdx.y][blockIdx.x] = sb[0];
    }
}

__global__ void k_wstat2() {
    __shared__ double sa[256];
    __shared__ double sb[256];
    double s1 = 0.0, s2 = 0.0;
    for (int i = threadIdx.x; i < 1024; i += 256) {
        s1 += g_red2a[blockIdx.x][i];
        s2 += g_red2b[blockIdx.x][i];
    }
    sa[threadIdx.x] = s1; sb[threadIdx.x] = s2;
    __syncthreads();
    for (int st = 128; st > 0; st >>= 1) {
        if (threadIdx.x < st) {
            sa[threadIdx.x] += sa[threadIdx.x + st];
            sb[threadIdx.x] += sb[threadIdx.x + st];
        }
        __syncthreads();
    }
    if (threadIdx.x == 0)
        g_alpha[blockIdx.x] = (float)(sa[0] / fmax(sb[0], 1.0));
}

__global__ void k_wtern(const float* __restrict__ W0, const float* __restrict__ W1,
                        const float* __restrict__ W2, const float* __restrict__ W3) {
    int y = blockIdx.y;
    const float* W = pick_w(W0, W1, W2, W3, y);
    float delta = g_delta[y];
    float alpha = g_alpha[y];
    int i = blockIdx.x * 1024 + threadIdx.x;
    float w = W[i];
    float a = fabsf(w);
    float t = 0.0f;
    if (a > delta) t = (w > 0.0f) ? alpha : -alpha;
    g_Wt[y][i] = t;
}

// ---------------------------------------------------------------------------
// SGEMM NT:  C[m][n] = scale * sum_k A[m][k] * B[n][k]  (+ bias[n])
// Tiles: BM=128, BN=128, BK=16, 256 threads, 8x8 micro-tile (split 4+4).
// z decomposes as (zb, zh) = (z>>4, z&15) for batched per-head launches.
// ---------------------------------------------------------------------------
__global__ void __launch_bounds__(256)
k_gemm_nt(const float* __restrict__ A, int lda, size_t sAb, size_t sAh,
          const float* __restrict__ B, int ldb, size_t sBb, size_t sBh,
          float* __restrict__ C, int ldc, size_t sCb, size_t sCh,
          const float* __restrict__ bias, float scale, int K) {
    int z = blockIdx.z, zb = z >> 4, zh = z & 15;
    A += (size_t)zb * sAb + (size_t)zh * sAh;
    B += (size_t)zb * sBb + (size_t)zh * sBh;
    C += (size_t)zb * sCb + (size_t)zh * sCh;

    __shared__ float As[16][128];
    __shared__ float Bs[16][128];

    int tid = threadIdx.x;
    int ty = tid >> 4, tx = tid & 15;
    int rowBase = blockIdx.x * 128;
    int colBase = blockIdx.y * 128;

    float acc[8][8];
#pragma unroll
    for (int i = 0; i < 8; i++)
#pragma unroll
        for (int j = 0; j < 8; j++) acc[i][j] = 0.0f;

    for (int k0 = 0; k0 < K; k0 += 16) {
#pragma unroll
        for (int l = 0; l < 2; l++) {
            int f = tid + l * 256;          // 0..511
            int row = f >> 2;               // 0..127
            int kq = f & 3;                 // float4 slot
            float4 va = *(const float4*)(A + (size_t)(rowBase + row) * lda + k0 + kq * 4);
            As[kq * 4 + 0][row] = va.x;
            As[kq * 4 + 1][row] = va.y;
            As[kq * 4 + 2][row] = va.z;
            As[kq * 4 + 3][row] = va.w;
            float4 vb = *(const float4*)(B + (size_t)(colBase + row) * ldb + k0 + kq * 4);
            Bs[kq * 4 + 0][row] = vb.x;
            Bs[kq * 4 + 1][row] = vb.y;
            Bs[kq * 4 + 2][row] = vb.z;
            Bs[kq * 4 + 3][row] = vb.w;
        }
        __syncthreads();
#pragma unroll
        for (int kk = 0; kk < 16; kk++) {
            float4 a0 = *(const float4*)&As[kk][ty * 4];
            float4 a1 = *(const float4*)&As[kk][64 + ty * 4];
            float4 b0 = *(const float4*)&Bs[kk][tx * 4];
            float4 b1 = *(const float4*)&Bs[kk][64 + tx * 4];
            float ar[8] = {a0.x, a0.y, a0.z, a0.w, a1.x, a1.y, a1.z, a1.w};
            float br[8] = {b0.x, b0.y, b0.z, b0.w, b1.x, b1.y, b1.z, b1.w};
#pragma unroll
            for (int i = 0; i < 8; i++)
#pragma unroll
                for (int j = 0; j < 8; j++)
                    acc[i][j] = fmaf(ar[i], br[j], acc[i][j]);
        }
        __syncthreads();
    }

#pragma unroll
    for (int i = 0; i < 8; i++) {
        int r = rowBase + ((i < 4) ? (ty * 4 + i) : (64 + ty * 4 + i - 4));
        float bb[8];
#pragma unroll
        for (int j = 0; j < 8; j++) {
            int c = colBase + ((j < 4) ? (tx * 4 + j) : (64 + tx * 4 + j - 4));
            bb[j] = bias ? bias[c] : 0.0f;
        }
        float4 v0 = make_float4(acc[i][0] * scale + bb[0], acc[i][1] * scale + bb[1],
                                acc[i][2] * scale + bb[2], acc[i][3] * scale + bb[3]);
        float4 v1 = make_float4(acc[i][4] * scale + bb[4], acc[i][5] * scale + bb[5],
                                acc[i][6] * scale + bb[6], acc[i][7] * scale + bb[7]);
        *(float4*)(C + (size_t)r * ldc + colBase + tx * 4) = v0;
        *(float4*)(C + (size_t)r * ldc + colBase + 64 + tx * 4) = v1;
    }
}

// ---------------------------------------------------------------------------
// SGEMM NN:  C[m][n] = sum_k A[m][k] * B[k][n]   (BM=128, BN=64, BK=16)
// Used for O = P @ V (N = Dh = 64).
// ---------------------------------------------------------------------------
__global__ void __launch_bounds__(256)
k_gemm_nn(const float* __restrict__ A, int lda, size_t sAb, size_t sAh,
          const float* __restrict__ B, int ldb, size_t sBb, size_t sBh,
          float* __restrict__ C, int ldc, size_t sCb, size_t sCh, int K) {
    int z = blockIdx.z, zb = z >> 4, zh = z & 15;
    A += (size_t)zb * sAb + (size_t)zh * sAh;
    B += (size_t)zb * sBb + (size_t)zh * sBh;
    C += (size_t)zb * sCb + (size_t)zh * sCh;

    __shared__ float As[16][128];
    __shared__ float Bs[16][64];

    int tid = threadIdx.x;
    int ty = tid >> 4, tx = tid & 15;
    int rowBase = blockIdx.x * 128;

    float acc[8][4];
#pragma unroll
    for (int i = 0; i < 8; i++)
#pragma unroll
        for (int j = 0; j < 4; j++) acc[i][j] = 0.0f;

    for (int k0 = 0; k0 < K; k0 += 16) {
#pragma unroll
        for (int l = 0; l < 2; l++) {
            int f = tid + l * 256;
            int row = f >> 2;
            int kq = f & 3;
            float4 va = *(const float4*)(A + (size_t)(rowBase + row) * lda + k0 + kq * 4);
            As[kq * 4 + 0][row] = va.x;
            As[kq * 4 + 1][row] = va.y;
            As[kq * 4 + 2][row] = va.z;
            As[kq * 4 + 3][row] = va.w;
        }
        {
            int krow = tid >> 4;   // 0..15
            int n4 = tid & 15;     // 0..15 -> 4-float chunk
            float4 vb = *(const float4*)(B + (size_t)(k0 + krow) * ldb + n4 * 4);
            *(float4*)&Bs[krow][n4 * 4] = vb;
        }
        __syncthreads();
#pragma unroll
        for (int kk = 0; kk < 16; kk++) {
            float4 a0 = *(const float4*)&As[kk][ty * 4];
            float4 a1 = *(const float4*)&As[kk][64 + ty * 4];
            float4 b = *(const float4*)&Bs[kk][tx * 4];
            float ar[8] = {a0.x, a0.y, a0.z, a0.w, a1.x, a1.y, a1.z, a1.w};
            float br[4] = {b.x, b.y, b.z, b.w};
#pragma unroll
            for (int i = 0; i < 8; i++)
#pragma unroll
                for (int j = 0; j < 4; j++)
                    acc[i][j] = fmaf(ar[i], br[j], acc[i][j]);
        }
        __syncthreads();
    }

#pragma unroll
    for (int i = 0; i < 8; i++) {
        int r = rowBase + ((i < 4) ? (ty * 4 + i) : (64 + ty * 4 + i - 4));
        float4 v = make_float4(acc[i][0], acc[i][1], acc[i][2], acc[i][3]);
        *(float4*)(C + (size_t)r * ldc + tx * 4) = v;
    }
}

// ---------------------------------------------------------------------------
// Row softmax over rows of length 2048 (in place), exact two-pass like jax.
// ---------------------------------------------------------------------------
__global__ void k_softmax(float* __restrict__ S) {
    size_t row = blockIdx.x;
    float* p = S + row * (size_t)T_LEN;
    __shared__ float sm[256];
    int tid = threadIdx.x;

    float v[8];
    float m = -INFINITY;
#pragma unroll
    for (int i = 0; i < 8; i++) {
        v[i] = p[tid + i * 256];
        m = fmaxf(m, v[i]);
    }
    sm[tid] = m;
    __syncthreads();
    for (int st = 128; st > 0; st >>= 1) {
        if (tid < st) sm[tid] = fmaxf(sm[tid], sm[tid + st]);
        __syncthreads();
    }
    m = sm[0];
    __syncthreads();

    float s = 0.0f;
#pragma unroll
    for (int i = 0; i < 8; i++) {
        v[i] = expf(v[i] - m);
        s += v[i];
    }
    sm[tid] = s;
    __syncthreads();
    for (int st = 128; st > 0; st >>= 1) {
        if (tid < st) sm[tid] += sm[tid + st];
        __syncthreads();
    }
    float total = sm[0];
#pragma unroll
    for (int i = 0; i < 8; i++)
        p[tid + i * 256] = v[i] / total;
}

// ---------------------------------------------------------------------------
// fp4 activation quant: scale = max(max|y| / 7, 1e-8); q = clip(rint(y/s)) * s
// ---------------------------------------------------------------------------
__global__ void k_absmax_partial(const float* __restrict__ Y) {
    __shared__ float sm[256];
    int base = blockIdx.x * 1024;
    int tid = threadIdx.x;
    float m = 0.0f;
#pragma unroll
    for (int i = 0; i < 4; i++)
        m = fmaxf(m, fabsf(Y[base + tid + i * 256]));
    sm[tid] = m;
    __syncthreads();
    for (int st = 128; st > 0; st >>= 1) {
        if (tid < st) sm[tid] = fmaxf(sm[tid], sm[tid + st]);
        __syncthreads();
    }
    if (tid == 0) g_maxp[blockIdx.x] = sm[0];
}

__global__ void k_absmax_final() {
    __shared__ float sm[1024];
    int tid = threadIdx.x;
    float m = 0.0f;
#pragma unroll
    for (int i = 0; i < 4; i++)
        m = fmaxf(m, g_maxp[tid + i * 1024]);
    sm[tid] = m;
    __syncthreads();
    for (int st = 512; st > 0; st >>= 1) {
        if (tid < st) sm[tid] = fmaxf(sm[tid], sm[tid + st]);
        __syncthreads();
    }
    if (tid == 0) g_scale = fmaxf(sm[0] / 7.0f, 1e-8f);
}

__global__ void k_quant(const float* __restrict__ Y, float* __restrict__ out) {
    int i = blockIdx.x * 1024 + threadIdx.x;
    float s = g_scale;
    float q = rintf(Y[i] / s);
    q = fminf(7.0f, fmaxf(-7.0f, q));
    out[i] = q * s;
}

// ---------------------------------------------------------------------------
// Launch
// ---------------------------------------------------------------------------
extern "C" void kernel_launch(void* const* d_in, const int* in_sizes, int n_in,
                              void* d_out, int out_size) {
    const float* x  = (const float*)d_in[0];
    const float* Wq = (const float*)d_in[1];
    const float* bq = (const float*)d_in[2];
    const float* Wk = (const float*)d_in[3];
    const float* bk = (const float*)d_in[4];
    const float* Wv = (const float*)d_in[5];
    const float* bv = (const float*)d_in[6];
    const float* Wo = (const float*)d_in[7];
    const float* bo = (const float*)d_in[8];
    float* out = (float*)d_out;

    // Resolve device scratch addresses (host-side symbol addresses of __device__ arrays)
    float* wt0; cudaGetSymbolAddress((void**)&wt0, g_Wt);
    float* wt1 = wt0 + (size_t)1 * W_ELEMS;
    float* wt2 = wt0 + (size_t)2 * W_ELEMS;
    float* wt3 = wt0 + (size_t)3 * W_ELEMS;
    float* q;  cudaGetSymbolAddress((void**)&q,  g_Q);
    float* k;  cudaGetSymbolAddress((void**)&k,  g_K);
    float* v;  cudaGetSymbolAddress((void**)&v,  g_V);
    float* o;  cudaGetSymbolAddress((void**)&o,  g_O);
    float* y;  cudaGetSymbolAddress((void**)&y,  g_Y);
    float* s;  cudaGetSymbolAddress((void**)&s,  g_S);

    // 1) Weight ternarization statistics
    k_wabs<<<dim3(1024, 4), 256>>>(Wq, Wk, Wv, Wo);
    k_wstat1<<<4, 256>>>();
    k_wmask<<<dim3(1024, 4), 256>>>(Wq, Wk, Wv, Wo);
    k_wstat2<<<4, 256>>>();
    k_wtern<<<dim3(1024, 4), 1024>>>(Wq, Wk, Wv, Wo);

    // 2) Projections: Q/K/V = x @ Wt^T + b   (M=4096, N=1024, K=1024)
    k_gemm_nt<<<dim3(32, 8, 1), 256>>>(x, D_MODEL, 0, 0,
                                       wt0, D_MODEL, 0, 0,
                                       q, D_MODEL, 0, 0, bq, 1.0f, D_MODEL);
    k_gemm_nt<<<dim3(32, 8, 1), 256>>>(x, D_MODEL, 0, 0,
                                       wt1, D_MODEL, 0, 0,
                                       k, D_MODEL, 0, 0, bk, 1.0f, D_MODEL);
    k_gemm_nt<<<dim3(32, 8, 1), 256>>>(x, D_MODEL, 0, 0,
                                       wt2, D_MODEL, 0, 0,
                                       v, D_MODEL, 0, 0, bv, 1.0f, D_MODEL);

    // 3) Scores: S[b,h] = (Q_bh @ K_bh^T) * 0.125   (M=N=2048, K=64, 32 batches)
    const size_t sQb = (size_t)T_LEN * D_MODEL;   // batch stride in Q/K/V/O
    const size_t sQh = (size_t)D_HEAD;            // head stride
    const size_t sSh = (size_t)T_LEN * T_LEN;     // head stride in S
    const size_t sSb = (size_t)N_HEADS * sSh;     // batch stride in S
    k_gemm_nt<<<dim3(16, 16, BATCH * N_HEADS), 256>>>(
        q, D_MODEL, sQb, sQh,
        k, D_MODEL, sQb, sQh,
        s, T_LEN, sSb, sSh, nullptr, 0.125f, D_HEAD);

    // 4) Softmax over rows of S
    k_softmax<<<BATCH * N_HEADS * T_LEN, 256>>>(s);

    // 5) O[b,h] = P @ V   (M=2048, N=64, K=2048)
    k_gemm_nn<<<dim3(16, 1, BATCH * N_HEADS), 256>>>(
        s, T_LEN, sSb, sSh,
        v, D_MODEL, sQb, sQh,
        o, D_MODEL, sQb, sQh, T_LEN);

    // 6) Output projection: Y = O @ Wt_o^T + bo
    k_gemm_nt<<<dim3(32, 8, 1), 256>>>(o, D_MODEL, 0, 0,
                                       wt3, D_MODEL, 0, 0,
                                       y, D_MODEL, 0, 0, bo, 1.0f, D_MODEL);

    // 7) fp4 activation quant -> d_out
    k_absmax_partial<<<4096, 256>>>(y);
    k_absmax_final<<<1, 1024>>>();
    k_quant<<<4096, 1024>>>(y, out);
}